// round 2
// baseline (speedup 1.0000x reference)
#include <cuda_runtime.h>
#include <math.h>

#define NB 128
#define NN 4096
#define KK 15
#define EPSV 0.1f
#define SMALLV 1e-20f
#define MUV 2.44140625e-4f   /* 1/4096 */
#define NITER 200

// ---------------- device scratch (static, no allocation) ----------------
__device__ float g_sig[NB * KK * NN];   // sigmoid+SMALL, layout [b][j][i]
__device__ float g_tv[NB * KK];         // top-15 values per row, descending
__device__ float g_colsum[NB * KK];     // per-(b,j) column sums of sig
__device__ float g_w[NB * 16];          // Sinkhorn state w_m
__device__ float g_t[NB * NN];          // final t_i
__device__ float g_mx[256], g_mn[256];
__device__ int   g_fl[256];
__device__ double g_norm;

struct Par { float filled, invCmax, alpha, inv_tau, c_exp2; };
__device__ Par g_P;

// ---------------- helpers ----------------
__device__ __forceinline__ float warp_sum(float v) {
#pragma unroll
    for (int o = 16; o > 0; o >>= 1) v += __shfl_xor_sync(0xffffffffu, v, o);
    return v;
}
__device__ __forceinline__ float warp_max(float v) {
#pragma unroll
    for (int o = 16; o > 0; o >>= 1) v = fmaxf(v, __shfl_xor_sync(0xffffffffu, v, o));
    return v;
}
__device__ __forceinline__ float warp_min(float v) {
#pragma unroll
    for (int o = 16; o > 0; o >>= 1) v = fminf(v, __shfl_xor_sync(0xffffffffu, v, o));
    return v;
}
__device__ __forceinline__ int warp_or(int v) {
#pragma unroll
    for (int o = 16; o > 0; o >>= 1) v |= __shfl_xor_sync(0xffffffffu, v, o);
    return v;
}
__device__ __forceinline__ float rcpa(float x) {
    float y; asm("rcp.approx.f32 %0, %1;" : "=f"(y) : "f"(x)); return y;
}
__device__ __forceinline__ float fixs(float s) {
    return (isinf(s) && s < 0.0f) ? g_P.filled : s;
}

// ---------------- A1: global min/max partials ----------------
__global__ void kA1(const float* __restrict__ scores) {
    int tid = threadIdx.x;
    int base = blockIdx.x * 2048 + tid * 8;
    const float4* p4 = reinterpret_cast<const float4*>(scores + base);
    float4 a = p4[0], b = p4[1];
    float vs[8] = {a.x, a.y, a.z, a.w, b.x, b.y, b.z, b.w};
    float mx = -3.4e38f, mn = 3.4e38f; int fl = 0;
#pragma unroll
    for (int t = 0; t < 8; t++) {
        float x = vs[t];
        if (isinf(x) && x < 0.0f) fl = 1;
        else mn = fminf(mn, x);
        mx = fmaxf(mx, x);
    }
    mx = warp_max(mx); mn = warp_min(mn); fl = warp_or(fl);
    __shared__ float smx[8], smn[8]; __shared__ int sfl[8];
    int lane = tid & 31, wid = tid >> 5;
    if (!lane) { smx[wid] = mx; smn[wid] = mn; sfl[wid] = fl; }
    __syncthreads();
    if (tid == 0) {
        for (int w = 1; w < 8; w++) { mx = fmaxf(mx, smx[w]); mn = fminf(mn, smn[w]); fl |= sfl[w]; }
        g_mx[blockIdx.x] = mx; g_mn[blockIdx.x] = mn; g_fl[blockIdx.x] = fl;
    }
}

// ---------------- A2: finalize scalar params ----------------
__global__ void kA2(const float* __restrict__ tau) {
    int tid = threadIdx.x, lane = tid & 31, wid = tid >> 5;
    float mx = g_mx[tid], mn = g_mn[tid]; int fl = g_fl[tid];
    mx = warp_max(mx); mn = warp_min(mn); fl = warp_or(fl);
    __shared__ float smx[8], smn[8]; __shared__ int sfl[8];
    if (!lane) { smx[wid] = mx; smn[wid] = mn; sfl[wid] = fl; }
    __syncthreads();
    if (tid == 0) {
        for (int w = 1; w < 8; w++) { mx = fmaxf(mx, smx[w]); mn = fminf(mn, smn[w]); fl |= sfl[w]; }
        float filled = mn - (mx - mn);
        float lo = fl ? filled : mn;
        float d1 = lo - 15.0f, d2 = mx - 15.0f;
        float Cmax = fmaxf(fmaxf(lo * lo, d1 * d1), fmaxf(mx * mx, d2 * d2));
        float invC = 1.0f / Cmax;
        float alpha = 10.0f * invC;         // invCmax / EPS
        Par P;
        P.filled = filled; P.invCmax = invC; P.alpha = alpha;
        P.inv_tau = 1.0f / tau[0];
        P.c_exp2 = 2.0f * alpha * 1.4426950408889634f;  // 2*alpha*log2(e)
        g_P = P;
        g_norm = 0.0;
    }
}

// ---------------- top-15 per row (15 masked-argmax rounds) ----------------
__global__ __launch_bounds__(512) void kTop(const float* __restrict__ scores) {
    int b = blockIdx.x, tid = threadIdx.x, lane = tid & 31, wid = tid >> 5;
    const float4* p4 = reinterpret_cast<const float4*>(scores + b * NN) + tid * 2;
    float4 a = p4[0], c4 = p4[1];
    float v[8] = {a.x, a.y, a.z, a.w, c4.x, c4.y, c4.z, c4.w};
#pragma unroll
    for (int e = 0; e < 8; e++) v[e] = fixs(v[e]);
    __shared__ float swm[16];
    __shared__ float sbc;
    __shared__ int claim;
    for (int r = 0; r < KK; r++) {
        float lm = v[0];
#pragma unroll
        for (int e = 1; e < 8; e++) lm = fmaxf(lm, v[e]);
        lm = warp_max(lm);
        if (!lane) swm[wid] = lm;
        __syncthreads();
        if (tid == 0) {
            float m = swm[0];
            for (int w = 1; w < 16; w++) m = fmaxf(m, swm[w]);
            sbc = m; claim = 0;
            g_tv[b * KK + r] = m;
        }
        __syncthreads();
        float m = sbc;
        int idx = -1;
#pragma unroll
        for (int e = 0; e < 8; e++) if (idx < 0 && v[e] == m) idx = e;
        if (idx >= 0) {
            int old = atomicAdd(&claim, 1);
            if (old == 0) v[idx] = -3.4e38f;
        }
        // removal/claim of this round completes before next round's tid0 reset
        // because reset happens after the first __syncthreads of the next round.
    }
}

// ---------------- sigmoids + column sums ----------------
__global__ __launch_bounds__(512) void kSig(const float* __restrict__ scores) {
    int b = blockIdx.x, tid = threadIdx.x, lane = tid & 31, wid = tid >> 5;
    __shared__ float stv[KK];
    if (tid < KK) stv[tid] = g_tv[b * KK + tid];
    __syncthreads();
    float itau = g_P.inv_tau;
    float cs[KK];
#pragma unroll
    for (int j = 0; j < KK; j++) cs[j] = 0.0f;
    for (int e = 0; e < 8; e++) {
        int i = tid + e * 512;
        float s = fixs(scores[b * NN + i]);
#pragma unroll
        for (int j = 0; j < KK; j++) {
            float d = fabsf(stv[j] - s) * itau;
            float ex = __expf(d);
            float sg = rcpa(1.0f + ex) + SMALLV;
            g_sig[(b * KK + j) * NN + i] = sg;
            cs[j] += sg;
        }
    }
#pragma unroll
    for (int j = 0; j < KK; j++) cs[j] = warp_sum(cs[j]);
    __shared__ float scs[16][KK];
    if (!lane) {
#pragma unroll
        for (int j = 0; j < KK; j++) scs[wid][j] = cs[j];
    }
    __syncthreads();
    if (tid < KK) {
        float a = 0.0f;
        for (int w = 0; w < 16; w++) a += scs[w][tid];
        g_colsum[b * KK + tid] = a;
    }
}

// ---------------- rank-5 projection -> initial w ----------------
__global__ __launch_bounds__(512) void kY(const float* __restrict__ scores,
                                          const float* __restrict__ w1,
                                          const float* __restrict__ w2) {
    int b = blockIdx.x, tid = threadIdx.x, lane = tid & 31, wid = tid >> 5;
    __shared__ float sinv[KK], lc[KK];
    if (tid < KK) {
        float c = g_colsum[b * KK + tid];
        sinv[tid] = 1.0f / c;
        lc[tid] = EPSV * __logf(4096.0f * c);
    }
    __syncthreads();
    float invC = g_P.invCmax;
    float y[5] = {0, 0, 0, 0, 0};
    for (int e = 0; e < 8; e++) {
        int i = tid + e * 512;
        float s = fixs(scores[b * NN + i]);
        float rowacc = 0.0f;
#pragma unroll
        for (int c = 0; c < KK; c++) {
            float sg = g_sig[(b * KK + c) * NN + i];
            float ds = s - (float)(KK - c);
            float bic = ds * ds * invC + EPSV * __logf(sg) - lc[c];
            rowacc += sg * sinv[c];
#pragma unroll
            for (int r = 0; r < 5; r++) y[r] += bic * w2[r * 65536 + i * 16 + c];
        }
        float last = (1.0f - rowacc) * MUV;
        last = fminf(fmaxf(last, SMALLV), 1.0f - SMALLV);
        float b15 = s * s * invC + EPSV * __logf(last);
#pragma unroll
        for (int r = 0; r < 5; r++) y[r] += b15 * w2[r * 65536 + i * 16 + 15];
    }
#pragma unroll
    for (int r = 0; r < 5; r++) y[r] = warp_sum(y[r]);
    __shared__ float sy[16][5];
    if (!lane) {
#pragma unroll
        for (int r = 0; r < 5; r++) sy[wid][r] = y[r];
    }
    __syncthreads();
    __shared__ float yf[5];
    if (tid < 5) {
        float a = 0.0f;
        for (int w = 0; w < 16; w++) a += sy[w][tid];
        yf[tid] = a;
    }
    __syncthreads();
    __shared__ float gg[KK];
    if (tid < KK) {
        float g = 0.0f;
#pragma unroll
        for (int r = 0; r < 5; r++) g += yf[r] * w1[(NN + tid) * 5 + r];
        gg[tid] = g;
    }
    __syncthreads();
    if (tid < 16) {
        int m = tid;
        float w = (m == 0) ? 1.0f
                 : __expf(10.0f * gg[KK - m] - g_P.alpha * (float)(m * m));
        g_w[b * 16 + m] = w;
    }
}

// ---------------- the 200-iteration Sinkhorn loop ----------------
__global__ __launch_bounds__(256) void kSink(const float* __restrict__ scores) {
    int b = blockIdx.x, tid = threadIdx.x, lane = tid & 31, wid = tid >> 5;  // 8 warps
    __shared__ float sS[8][16];
    __shared__ float sW[16];
    float c2 = g_P.c_exp2;
    float p[16];
#pragma unroll
    for (int e = 0; e < 16; e++) {
        float s = fixs(scores[b * NN + tid + e * 256]);
        p[e] = exp2f(c2 * s);
    }
    if (tid < 16) sW[tid] = g_w[b * 16 + tid];
    __syncthreads();
    float w[16];
#pragma unroll
    for (int m = 0; m < 16; m++) w[m] = sW[m];

    for (int it = 0; it < NITER; it++) {
        float S[16];
#pragma unroll
        for (int m = 0; m < 16; m++) S[m] = 0.0f;
#pragma unroll
        for (int e = 0; e < 16; e++) {
            float x = p[e];
            float H = w[15];
#pragma unroll
            for (int m = 14; m >= 0; m--) H = fmaf(H, x, w[m]);
            float t = MUV * rcpa(H);
            if (it == NITER - 1) g_t[b * NN + tid + e * 256] = t;
            float r = t;
            S[0] += r;
#pragma unroll
            for (int m = 1; m < 16; m++) { r *= x; S[m] += r; }
        }
#pragma unroll
        for (int m = 0; m < 16; m++) S[m] = warp_sum(S[m]);
        if (!lane) {
#pragma unroll
            for (int m = 0; m < 16; m++) sS[wid][m] = S[m];
        }
        __syncthreads();
        if (tid < 16) {
            float a = 0.0f;
#pragma unroll
            for (int q = 0; q < 8; q++) a += sS[q][tid];
            float nu = (tid == 0) ? (4081.0f / 4096.0f) : MUV;
            sW[tid] = nu * rcpa(a);
        }
        __syncthreads();
#pragma unroll
        for (int m = 0; m < 16; m++) w[m] = sW[m];
    }
    if (tid < 16) g_w[b * 16 + tid] = w[tid];
}

// ---------------- output: A and norm partials ----------------
__global__ __launch_bounds__(512) void kOut(const float* __restrict__ scores,
                                            float* __restrict__ out) {
    int b = blockIdx.x, tid = threadIdx.x, lane = tid & 31, wid = tid >> 5;
    __shared__ float sW[16], sinv[KK];
    if (tid < 16) sW[tid] = g_w[b * 16 + tid];
    if (tid < KK) sinv[tid] = 1.0f / g_colsum[b * KK + tid];
    __syncthreads();
    float w[16];
#pragma unroll
    for (int m = 0; m < 16; m++) w[m] = sW[m];
    float c2 = g_P.c_exp2;
    float nacc = 0.0f;
    for (int e = 0; e < 8; e++) {
        int i = tid + e * 512;
        float s = fixs(scores[b * NN + i]);
        float x = exp2f(c2 * s);
        float t = g_t[b * NN + i];
        float gam[16];
        gam[0] = t * w[0];
        float r = t;
#pragma unroll
        for (int m = 1; m < 16; m++) { r *= x; gam[m] = r * w[m]; }
        float* Ao = out + ((size_t)(b * NN + i)) * 15;
#pragma unroll
        for (int c = 0; c < KK; c++) Ao[c] = 4096.0f * gam[15 - c];
        float rowacc = 0.0f;
#pragma unroll
        for (int c = 0; c < KK; c++) {
            float sg = g_sig[(b * KK + c) * NN + i];
            float sn = sg * sinv[c];
            rowacc += sn;
            float g0 = sn * MUV;
            float d = gam[15 - c] - g0;
            nacc += d * d;
        }
        float last = (1.0f - rowacc) * MUV;
        last = fminf(fmaxf(last, SMALLV), 1.0f - SMALLV);
        float d = gam[0] - last;
        nacc += d * d;
    }
    nacc = warp_sum(nacc);
    __shared__ float sn_[16];
    if (!lane) sn_[wid] = nacc;
    __syncthreads();
    if (tid == 0) {
        float a = 0.0f;
        for (int q = 0; q < 16; q++) a += sn_[q];
        atomicAdd(&g_norm, (double)a);
    }
}

__global__ void kFin(float* __restrict__ out, int out_size) {
    if (threadIdx.x == 0) out[out_size - 1] = sqrtf((float)g_norm);
}

extern "C" void kernel_launch(void* const* d_in, const int* in_sizes, int n_in,
                              void* d_out, int out_size) {
    const float* scores = (const float*)d_in[0];
    const float* tau    = (const float*)d_in[1];
    const float* w1     = (const float*)d_in[2];
    const float* w2     = (const float*)d_in[3];
    float* out = (float*)d_out;
    kA1<<<256, 256>>>(scores);
    kA2<<<1, 256>>>(tau);
    kTop<<<NB, 512>>>(scores);
    kSig<<<NB, 512>>>(scores);
    kY<<<NB, 512>>>(scores, w1, w2);
    kSink<<<NB, 256>>>(scores);
    kOut<<<NB, 512>>>(scores, out);
    kFin<<<1, 1>>>(out, out_size);
}

// round 3
// speedup vs baseline: 1.1895x; 1.1895x over previous
#include <cuda_runtime.h>
#include <math.h>

#define NB 128
#define NN 4096
#define KK 15
#define EPSV 0.1f
#define SMALLV 1e-20f
#define MUV 2.44140625e-4f   /* 1/4096 */
#define NITER 200

typedef unsigned long long ull;

// ---------------- device scratch (static, no allocation) ----------------
__device__ float g_sig[NB * KK * NN];   // sigmoid+SMALL, layout [b][j][i]
__device__ float g_tv[NB * KK];         // top-15 values per row, descending
__device__ float g_colsum[NB * KK];     // per-(b,j) column sums of sig
__device__ float g_w[NB * 16];          // Sinkhorn state w_m
__device__ float g_t[NB * NN];          // final t_i
__device__ float g_mx[256], g_mn[256];
__device__ int   g_fl[256];
__device__ double g_norm;

struct Par { float filled, invCmax, alpha, inv_tau, c_exp2; };
__device__ Par g_P;

// ---------------- helpers ----------------
__device__ __forceinline__ float warp_sum(float v) {
#pragma unroll
    for (int o = 16; o > 0; o >>= 1) v += __shfl_xor_sync(0xffffffffu, v, o);
    return v;
}
__device__ __forceinline__ float warp_max(float v) {
#pragma unroll
    for (int o = 16; o > 0; o >>= 1) v = fmaxf(v, __shfl_xor_sync(0xffffffffu, v, o));
    return v;
}
__device__ __forceinline__ float warp_min(float v) {
#pragma unroll
    for (int o = 16; o > 0; o >>= 1) v = fminf(v, __shfl_xor_sync(0xffffffffu, v, o));
    return v;
}
__device__ __forceinline__ int warp_or(int v) {
#pragma unroll
    for (int o = 16; o > 0; o >>= 1) v |= __shfl_xor_sync(0xffffffffu, v, o);
    return v;
}
__device__ __forceinline__ float rcpa(float x) {
    float y; asm("rcp.approx.f32 %0, %1;" : "=f"(y) : "f"(x)); return y;
}
__device__ __forceinline__ float fixs(float s) {
    return (isinf(s) && s < 0.0f) ? g_P.filled : s;
}

// ---------------- packed f32x2 (sm_103a) ----------------
__device__ __forceinline__ ull pk2(float lo, float hi) {
    ull r; asm("mov.b64 %0, {%1,%2};" : "=l"(r) : "f"(lo), "f"(hi)); return r;
}
__device__ __forceinline__ void upk2(float& lo, float& hi, ull v) {
    asm("mov.b64 {%0,%1}, %2;" : "=f"(lo), "=f"(hi) : "l"(v));
}
__device__ __forceinline__ ull fma2(ull a, ull b, ull c) {
    ull d; asm("fma.rn.f32x2 %0, %1, %2, %3;" : "=l"(d) : "l"(a), "l"(b), "l"(c)); return d;
}
__device__ __forceinline__ ull mul2(ull a, ull b) {
    ull d; asm("mul.rn.f32x2 %0, %1, %2;" : "=l"(d) : "l"(a), "l"(b)); return d;
}
__device__ __forceinline__ ull add2(ull a, ull b) {
    ull d; asm("add.rn.f32x2 %0, %1, %2;" : "=l"(d) : "l"(a), "l"(b)); return d;
}

// ---------------- A1: global min/max partials ----------------
__global__ void kA1(const float* __restrict__ scores) {
    int tid = threadIdx.x;
    int base = blockIdx.x * 2048 + tid * 8;
    const float4* p4 = reinterpret_cast<const float4*>(scores + base);
    float4 a = p4[0], b = p4[1];
    float vs[8] = {a.x, a.y, a.z, a.w, b.x, b.y, b.z, b.w};
    float mx = -3.4e38f, mn = 3.4e38f; int fl = 0;
#pragma unroll
    for (int t = 0; t < 8; t++) {
        float x = vs[t];
        if (isinf(x) && x < 0.0f) fl = 1;
        else mn = fminf(mn, x);
        mx = fmaxf(mx, x);
    }
    mx = warp_max(mx); mn = warp_min(mn); fl = warp_or(fl);
    __shared__ float smx[8], smn[8]; __shared__ int sfl[8];
    int lane = tid & 31, wid = tid >> 5;
    if (!lane) { smx[wid] = mx; smn[wid] = mn; sfl[wid] = fl; }
    __syncthreads();
    if (tid == 0) {
        for (int w = 1; w < 8; w++) { mx = fmaxf(mx, smx[w]); mn = fminf(mn, smn[w]); fl |= sfl[w]; }
        g_mx[blockIdx.x] = mx; g_mn[blockIdx.x] = mn; g_fl[blockIdx.x] = fl;
    }
}

// ---------------- A2: finalize scalar params ----------------
__global__ void kA2(const float* __restrict__ tau) {
    int tid = threadIdx.x, lane = tid & 31, wid = tid >> 5;
    float mx = g_mx[tid], mn = g_mn[tid]; int fl = g_fl[tid];
    mx = warp_max(mx); mn = warp_min(mn); fl = warp_or(fl);
    __shared__ float smx[8], smn[8]; __shared__ int sfl[8];
    if (!lane) { smx[wid] = mx; smn[wid] = mn; sfl[wid] = fl; }
    __syncthreads();
    if (tid == 0) {
        for (int w = 1; w < 8; w++) { mx = fmaxf(mx, smx[w]); mn = fminf(mn, smn[w]); fl |= sfl[w]; }
        float filled = mn - (mx - mn);
        float lo = fl ? filled : mn;
        float d1 = lo - 15.0f, d2 = mx - 15.0f;
        float Cmax = fmaxf(fmaxf(lo * lo, d1 * d1), fmaxf(mx * mx, d2 * d2));
        float invC = 1.0f / Cmax;
        float alpha = 10.0f * invC;         // invCmax / EPS
        Par P;
        P.filled = filled; P.invCmax = invC; P.alpha = alpha;
        P.inv_tau = 1.0f / tau[0];
        P.c_exp2 = 2.0f * alpha * 1.4426950408889634f;  // 2*alpha*log2(e)
        g_P = P;
        g_norm = 0.0;
    }
}

// ---------------- top-15 per row (15 masked-argmax rounds) ----------------
__global__ __launch_bounds__(512) void kTop(const float* __restrict__ scores) {
    int b = blockIdx.x, tid = threadIdx.x, lane = tid & 31, wid = tid >> 5;
    const float4* p4 = reinterpret_cast<const float4*>(scores + b * NN) + tid * 2;
    float4 a = p4[0], c4 = p4[1];
    float v[8] = {a.x, a.y, a.z, a.w, c4.x, c4.y, c4.z, c4.w};
#pragma unroll
    for (int e = 0; e < 8; e++) v[e] = fixs(v[e]);
    __shared__ float swm[16];
    __shared__ float sbc;
    __shared__ int claim;
    for (int r = 0; r < KK; r++) {
        float lm = v[0];
#pragma unroll
        for (int e = 1; e < 8; e++) lm = fmaxf(lm, v[e]);
        lm = warp_max(lm);
        if (!lane) swm[wid] = lm;
        __syncthreads();
        if (tid == 0) {
            float m = swm[0];
            for (int w = 1; w < 16; w++) m = fmaxf(m, swm[w]);
            sbc = m; claim = 0;
            g_tv[b * KK + r] = m;
        }
        __syncthreads();
        float m = sbc;
        int idx = -1;
#pragma unroll
        for (int e = 0; e < 8; e++) if (idx < 0 && v[e] == m) idx = e;
        if (idx >= 0) {
            int old = atomicAdd(&claim, 1);
            if (old == 0) v[idx] = -3.4e38f;
        }
    }
}

// ---------------- sigmoids + column sums ----------------
__global__ __launch_bounds__(512) void kSig(const float* __restrict__ scores) {
    int b = blockIdx.x, tid = threadIdx.x, lane = tid & 31, wid = tid >> 5;
    __shared__ float stv[KK];
    if (tid < KK) stv[tid] = g_tv[b * KK + tid];
    __syncthreads();
    float itau = g_P.inv_tau;
    float cs[KK];
#pragma unroll
    for (int j = 0; j < KK; j++) cs[j] = 0.0f;
    for (int e = 0; e < 8; e++) {
        int i = tid + e * 512;
        float s = fixs(scores[b * NN + i]);
#pragma unroll
        for (int j = 0; j < KK; j++) {
            float d = fabsf(stv[j] - s) * itau;
            float ex = __expf(d);
            float sg = rcpa(1.0f + ex) + SMALLV;
            g_sig[(b * KK + j) * NN + i] = sg;
            cs[j] += sg;
        }
    }
#pragma unroll
    for (int j = 0; j < KK; j++) cs[j] = warp_sum(cs[j]);
    __shared__ float scs[16][KK];
    if (!lane) {
#pragma unroll
        for (int j = 0; j < KK; j++) scs[wid][j] = cs[j];
    }
    __syncthreads();
    if (tid < KK) {
        float a = 0.0f;
        for (int w = 0; w < 16; w++) a += scs[w][tid];
        g_colsum[b * KK + tid] = a;
    }
}

// ---------------- rank-5 projection -> initial w ----------------
__global__ __launch_bounds__(512) void kY(const float* __restrict__ scores,
                                          const float* __restrict__ w1,
                                          const float* __restrict__ w2) {
    int b = blockIdx.x, tid = threadIdx.x, lane = tid & 31, wid = tid >> 5;
    __shared__ float sinv[KK], lc[KK];
    if (tid < KK) {
        float c = g_colsum[b * KK + tid];
        sinv[tid] = 1.0f / c;
        lc[tid] = EPSV * __logf(4096.0f * c);
    }
    __syncthreads();
    float invC = g_P.invCmax;
    float y[5] = {0, 0, 0, 0, 0};
    for (int e = 0; e < 8; e++) {
        int i = tid + e * 512;
        float s = fixs(scores[b * NN + i]);
        float rowacc = 0.0f;
#pragma unroll
        for (int c = 0; c < KK; c++) {
            float sg = g_sig[(b * KK + c) * NN + i];
            float ds = s - (float)(KK - c);
            float bic = ds * ds * invC + EPSV * __logf(sg) - lc[c];
            rowacc += sg * sinv[c];
#pragma unroll
            for (int r = 0; r < 5; r++) y[r] += bic * w2[r * 65536 + i * 16 + c];
        }
        float last = (1.0f - rowacc) * MUV;
        last = fminf(fmaxf(last, SMALLV), 1.0f - SMALLV);
        float b15 = s * s * invC + EPSV * __logf(last);
#pragma unroll
        for (int r = 0; r < 5; r++) y[r] += b15 * w2[r * 65536 + i * 16 + 15];
    }
#pragma unroll
    for (int r = 0; r < 5; r++) y[r] = warp_sum(y[r]);
    __shared__ float sy[16][5];
    if (!lane) {
#pragma unroll
        for (int r = 0; r < 5; r++) sy[wid][r] = y[r];
    }
    __syncthreads();
    __shared__ float yf[5];
    if (tid < 5) {
        float a = 0.0f;
        for (int w = 0; w < 16; w++) a += sy[w][tid];
        yf[tid] = a;
    }
    __syncthreads();
    __shared__ float gg[KK];
    if (tid < KK) {
        float g = 0.0f;
#pragma unroll
        for (int r = 0; r < 5; r++) g += yf[r] * w1[(NN + tid) * 5 + r];
        gg[tid] = g;
    }
    __syncthreads();
    if (tid < 16) {
        int m = tid;
        float w = (m == 0) ? 1.0f
                 : __expf(10.0f * gg[KK - m] - g_P.alpha * (float)(m * m));
        g_w[b * 16 + m] = w;
    }
}

// ---------------- the 200-iteration Sinkhorn loop (f32x2 packed) ----------------
__global__ __launch_bounds__(256, 1) void kSink(const float* __restrict__ scores) {
    int b = blockIdx.x, tid = threadIdx.x, lane = tid & 31, wid = tid >> 5;  // 8 warps
    __shared__ float sS[8][16];
    __shared__ float sW[16];
    float c2 = g_P.c_exp2;
    const float2* sc2 = reinterpret_cast<const float2*>(scores + b * NN);
    float2* t2out = reinterpret_cast<float2*>(g_t + b * NN);

    // p values as 8 packed pairs; precompute even powers x^2..x^14 (iteration-invariant)
    ull X[8];       // x
    ull P[8][7];    // x^2, x^4, ..., x^14
#pragma unroll
    for (int p = 0; p < 8; p++) {
        float2 s = sc2[tid + p * 256];
        float xlo = exp2f(c2 * fixs(s.x));
        float xhi = exp2f(c2 * fixs(s.y));
        ull x = pk2(xlo, xhi);
        X[p] = x;
        ull x2 = mul2(x, x);
        P[p][0] = x2;
#pragma unroll
        for (int j = 1; j < 7; j++) P[p][j] = mul2(P[p][j - 1], x2);
    }
    if (tid < 16) sW[tid] = g_w[b * 16 + tid];
    __syncthreads();
    ull W[16];
#pragma unroll
    for (int m = 0; m < 16; m++) { float v = sW[m]; W[m] = pk2(v, v); }

    for (int it = 0; it < NITER; it++) {
        ull S[16];
#pragma unroll
        for (int m = 0; m < 16; m++) S[m] = 0ull;
#pragma unroll
        for (int p = 0; p < 8; p++) {
            ull x2 = P[p][0];
            // H = A(x^2) + x*B(x^2); A coeffs w0,w2..w14, B coeffs w1,w3..w15
            ull A = W[14], B = W[15];
#pragma unroll
            for (int j = 6; j >= 1; j--) {
                A = fma2(A, x2, W[2 * j]);
                B = fma2(B, x2, W[2 * j + 1]);
            }
            A = fma2(A, x2, W[0]);
            B = fma2(B, x2, W[1]);
            ull H = fma2(X[p], B, A);
            float hlo, hhi; upk2(hlo, hhi, H);
            float tlo = MUV * rcpa(hlo);
            float thi = MUV * rcpa(hhi);
            if (it == NITER - 1) t2out[tid + p * 256] = make_float2(tlo, thi);
            ull t = pk2(tlo, thi);
            ull tx = mul2(t, X[p]);
            S[0] = add2(S[0], t);
            S[1] = add2(S[1], tx);
#pragma unroll
            for (int j = 1; j < 8; j++) {
                S[2 * j]     = fma2(t,  P[p][j - 1], S[2 * j]);
                S[2 * j + 1] = fma2(tx, P[p][j - 1], S[2 * j + 1]);
            }
        }
        float Sf[16];
#pragma unroll
        for (int m = 0; m < 16; m++) { float lo, hi; upk2(lo, hi, S[m]); Sf[m] = lo + hi; }
#pragma unroll
        for (int m = 0; m < 16; m++) Sf[m] = warp_sum(Sf[m]);
        if (!lane) {
#pragma unroll
            for (int m = 0; m < 16; m++) sS[wid][m] = Sf[m];
        }
        __syncthreads();
        if (tid < 16) {
            float a = 0.0f;
#pragma unroll
            for (int q = 0; q < 8; q++) a += sS[q][tid];
            float nu = (tid == 0) ? (4081.0f / 4096.0f) : MUV;
            sW[tid] = nu * rcpa(a);
        }
        __syncthreads();
#pragma unroll
        for (int m = 0; m < 16; m++) { float v = sW[m]; W[m] = pk2(v, v); }
    }
    if (tid < 16) g_w[b * 16 + tid] = sW[tid];
}

// ---------------- output: A and norm partials ----------------
__global__ __launch_bounds__(512) void kOut(const float* __restrict__ scores,
                                            float* __restrict__ out) {
    int b = blockIdx.x, tid = threadIdx.x, lane = tid & 31, wid = tid >> 5;
    __shared__ float sW[16], sinv[KK];
    if (tid < 16) sW[tid] = g_w[b * 16 + tid];
    if (tid < KK) sinv[tid] = 1.0f / g_colsum[b * KK + tid];
    __syncthreads();
    float w[16];
#pragma unroll
    for (int m = 0; m < 16; m++) w[m] = sW[m];
    float c2 = g_P.c_exp2;
    float nacc = 0.0f;
    for (int e = 0; e < 8; e++) {
        int i = tid + e * 512;
        float s = fixs(scores[b * NN + i]);
        float x = exp2f(c2 * s);
        float t = g_t[b * NN + i];
        float gam[16];
        gam[0] = t * w[0];
        float r = t;
#pragma unroll
        for (int m = 1; m < 16; m++) { r *= x; gam[m] = r * w[m]; }
        float* Ao = out + ((size_t)(b * NN + i)) * 15;
#pragma unroll
        for (int c = 0; c < KK; c++) Ao[c] = 4096.0f * gam[15 - c];
        float rowacc = 0.0f;
#pragma unroll
        for (int c = 0; c < KK; c++) {
            float sg = g_sig[(b * KK + c) * NN + i];
            float sn = sg * sinv[c];
            rowacc += sn;
            float g0 = sn * MUV;
            float d = gam[15 - c] - g0;
            nacc += d * d;
        }
        float last = (1.0f - rowacc) * MUV;
        last = fminf(fmaxf(last, SMALLV), 1.0f - SMALLV);
        float d = gam[0] - last;
        nacc += d * d;
    }
    nacc = warp_sum(nacc);
    __shared__ float sn_[16];
    if (!lane) sn_[wid] = nacc;
    __syncthreads();
    if (tid == 0) {
        float a = 0.0f;
        for (int q = 0; q < 16; q++) a += sn_[q];
        atomicAdd(&g_norm, (double)a);
    }
}

__global__ void kFin(float* __restrict__ out, int out_size) {
    if (threadIdx.x == 0) out[out_size - 1] = sqrtf((float)g_norm);
}

extern "C" void kernel_launch(void* const* d_in, const int* in_sizes, int n_in,
                              void* d_out, int out_size) {
    const float* scores = (const float*)d_in[0];
    const float* tau    = (const float*)d_in[1];
    const float* w1     = (const float*)d_in[2];
    const float* w2     = (const float*)d_in[3];
    float* out = (float*)d_out;
    kA1<<<256, 256>>>(scores);
    kA2<<<1, 256>>>(tau);
    kTop<<<NB, 512>>>(scores);
    kSig<<<NB, 512>>>(scores);
    kY<<<NB, 512>>>(scores, w1, w2);
    kSink<<<NB, 256>>>(scores);
    kOut<<<NB, 512>>>(scores, out);
    kFin<<<1, 1>>>(out, out_size);
}

// round 4
// speedup vs baseline: 1.3691x; 1.1509x over previous
#include <cuda_runtime.h>
#include <math.h>

#define NB 128
#define NN 4096
#define KK 15
#define EPSV 0.1f
#define SMALLV 1e-20f
#define MUV 2.44140625e-4f   /* 1/4096 */
#define NU0 (4081.0f/4096.0f)
#define NITER 200

typedef unsigned long long ull;

// ---------------- device scratch (static, no allocation) ----------------
__device__ float g_sig[NB * KK * NN];   // sigmoid+SMALL, layout [b][j][i]
__device__ float g_colsum[NB * KK];     // per-(b,j) column sums of sig
__device__ float g_w[NB * 16];          // initial Sinkhorn state w_m
__device__ float g_t[NB * NN];          // t_i from final iteration
__device__ float g_mx[256], g_mn[256];
__device__ int   g_fl[256];
__device__ double g_norm;

struct Par { float filled, invCmax, alpha, inv_tau, c_exp2; };
__device__ Par g_P;

// ---------------- helpers ----------------
__device__ __forceinline__ float warp_sum(float v) {
#pragma unroll
    for (int o = 16; o > 0; o >>= 1) v += __shfl_xor_sync(0xffffffffu, v, o);
    return v;
}
__device__ __forceinline__ float warp_max(float v) {
#pragma unroll
    for (int o = 16; o > 0; o >>= 1) v = fmaxf(v, __shfl_xor_sync(0xffffffffu, v, o));
    return v;
}
__device__ __forceinline__ float warp_min(float v) {
#pragma unroll
    for (int o = 16; o > 0; o >>= 1) v = fminf(v, __shfl_xor_sync(0xffffffffu, v, o));
    return v;
}
__device__ __forceinline__ int warp_or(int v) {
#pragma unroll
    for (int o = 16; o > 0; o >>= 1) v |= __shfl_xor_sync(0xffffffffu, v, o);
    return v;
}
__device__ __forceinline__ float rcpa(float x) {
    float y; asm("rcp.approx.f32 %0, %1;" : "=f"(y) : "f"(x)); return y;
}
__device__ __forceinline__ float fixs(float s) {
    return (isinf(s) && s < 0.0f) ? g_P.filled : s;
}

// ---------------- packed f32x2 (sm_103a) ----------------
__device__ __forceinline__ ull pk2(float lo, float hi) {
    ull r; asm("mov.b64 %0, {%1,%2};" : "=l"(r) : "f"(lo), "f"(hi)); return r;
}
__device__ __forceinline__ void upk2(float& lo, float& hi, ull v) {
    asm("mov.b64 {%0,%1}, %2;" : "=f"(lo), "=f"(hi) : "l"(v));
}
__device__ __forceinline__ ull fma2(ull a, ull b, ull c) {
    ull d; asm("fma.rn.f32x2 %0, %1, %2, %3;" : "=l"(d) : "l"(a), "l"(b), "l"(c)); return d;
}
__device__ __forceinline__ ull mul2(ull a, ull b) {
    ull d; asm("mul.rn.f32x2 %0, %1, %2;" : "=l"(d) : "l"(a), "l"(b)); return d;
}
__device__ __forceinline__ ull add2(ull a, ull b) {
    ull d; asm("add.rn.f32x2 %0, %1, %2;" : "=l"(d) : "l"(a), "l"(b)); return d;
}

// ---------------- A1: global min/max partials ----------------
__global__ void kA1(const float* __restrict__ scores) {
    int tid = threadIdx.x;
    int base = blockIdx.x * 2048 + tid * 8;
    const float4* p4 = reinterpret_cast<const float4*>(scores + base);
    float4 a = p4[0], b = p4[1];
    float vs[8] = {a.x, a.y, a.z, a.w, b.x, b.y, b.z, b.w};
    float mx = -3.4e38f, mn = 3.4e38f; int fl = 0;
#pragma unroll
    for (int t = 0; t < 8; t++) {
        float x = vs[t];
        if (isinf(x) && x < 0.0f) fl = 1;
        else mn = fminf(mn, x);
        mx = fmaxf(mx, x);
    }
    mx = warp_max(mx); mn = warp_min(mn); fl = warp_or(fl);
    __shared__ float smx[8], smn[8]; __shared__ int sfl[8];
    int lane = tid & 31, wid = tid >> 5;
    if (!lane) { smx[wid] = mx; smn[wid] = mn; sfl[wid] = fl; }
    __syncthreads();
    if (tid == 0) {
        for (int w = 1; w < 8; w++) { mx = fmaxf(mx, smx[w]); mn = fminf(mn, smn[w]); fl |= sfl[w]; }
        g_mx[blockIdx.x] = mx; g_mn[blockIdx.x] = mn; g_fl[blockIdx.x] = fl;
    }
}

// ---------------- A2: finalize scalar params ----------------
__global__ void kA2(const float* __restrict__ tau) {
    int tid = threadIdx.x, lane = tid & 31, wid = tid >> 5;
    float mx = g_mx[tid], mn = g_mn[tid]; int fl = g_fl[tid];
    mx = warp_max(mx); mn = warp_min(mn); fl = warp_or(fl);
    __shared__ float smx[8], smn[8]; __shared__ int sfl[8];
    if (!lane) { smx[wid] = mx; smn[wid] = mn; sfl[wid] = fl; }
    __syncthreads();
    if (tid == 0) {
        for (int w = 1; w < 8; w++) { mx = fmaxf(mx, smx[w]); mn = fminf(mn, smn[w]); fl |= sfl[w]; }
        float filled = mn - (mx - mn);
        float lo = fl ? filled : mn;
        float d1 = lo - 15.0f, d2 = mx - 15.0f;
        float Cmax = fmaxf(fmaxf(lo * lo, d1 * d1), fmaxf(mx * mx, d2 * d2));
        float invC = 1.0f / Cmax;
        Par P;
        P.filled = filled; P.invCmax = invC; P.alpha = 10.0f * invC;
        P.inv_tau = 1.0f / tau[0];
        P.c_exp2 = 2.0f * (10.0f * invC) * 1.4426950408889634f;
        g_P = P;
        g_norm = 0.0;
    }
}

// ---------------- fused prepass: top-15, sigmoids+colsums, rank-5 warm start ----------------
__global__ __launch_bounds__(512) void kPre(const float* __restrict__ scores,
                                            const float* __restrict__ w1,
                                            const float* __restrict__ w2) {
    int b = blockIdx.x, tid = threadIdx.x, lane = tid & 31, wid = tid >> 5;
    __shared__ float stv[KK];
    __shared__ float swm[16];
    __shared__ float sbc;
    __shared__ int claim;
    __shared__ float scs[16][KK];
    __shared__ float sinv[KK], lc[KK];
    __shared__ float sy[16][5];
    __shared__ float yf[5];
    __shared__ float gg[KK];

    // ---- phase A: top-15 via 15 masked argmax rounds ----
    {
        const float4* p4 = reinterpret_cast<const float4*>(scores + b * NN) + tid * 2;
        float4 a = p4[0], c4 = p4[1];
        float v[8] = {a.x, a.y, a.z, a.w, c4.x, c4.y, c4.z, c4.w};
#pragma unroll
        for (int e = 0; e < 8; e++) v[e] = fixs(v[e]);
        for (int r = 0; r < KK; r++) {
            float lm = v[0];
#pragma unroll
            for (int e = 1; e < 8; e++) lm = fmaxf(lm, v[e]);
            lm = warp_max(lm);
            if (!lane) swm[wid] = lm;
            __syncthreads();
            if (tid == 0) {
                float m = swm[0];
                for (int w = 1; w < 16; w++) m = fmaxf(m, swm[w]);
                sbc = m; claim = 0;
                stv[r] = m;
            }
            __syncthreads();
            float m = sbc;
            int idx = -1;
#pragma unroll
            for (int e = 0; e < 8; e++) if (idx < 0 && v[e] == m) idx = e;
            if (idx >= 0) {
                int old = atomicAdd(&claim, 1);
                if (old == 0) v[idx] = -3.4e38f;
            }
        }
    }
    __syncthreads();

    // ---- phase B: sigmoids + column sums ----
    {
        float itau = g_P.inv_tau;
        float cs[KK];
#pragma unroll
        for (int j = 0; j < KK; j++) cs[j] = 0.0f;
        for (int e = 0; e < 8; e++) {
            int i = tid + e * 512;
            float s = fixs(scores[b * NN + i]);
#pragma unroll
            for (int j = 0; j < KK; j++) {
                float d = fabsf(stv[j] - s) * itau;
                float ex = __expf(d);
                float sg = rcpa(1.0f + ex) + SMALLV;
                g_sig[(b * KK + j) * NN + i] = sg;
                cs[j] += sg;
            }
        }
#pragma unroll
        for (int j = 0; j < KK; j++) cs[j] = warp_sum(cs[j]);
        if (!lane) {
#pragma unroll
            for (int j = 0; j < KK; j++) scs[wid][j] = cs[j];
        }
        __syncthreads();
        if (tid < KK) {
            float a = 0.0f;
            for (int w = 0; w < 16; w++) a += scs[w][tid];
            g_colsum[b * KK + tid] = a;
            sinv[tid] = 1.0f / a;
            lc[tid] = EPSV * __logf(4096.0f * a);
        }
    }
    __syncthreads();

    // ---- phase C: rank-5 projection -> initial w ----
    {
        float invC = g_P.invCmax;
        float y[5] = {0, 0, 0, 0, 0};
        for (int e = 0; e < 8; e++) {
            int i = tid + e * 512;
            float s = fixs(scores[b * NN + i]);
            float rowacc = 0.0f;
#pragma unroll
            for (int c = 0; c < KK; c++) {
                float sg = g_sig[(b * KK + c) * NN + i];
                float ds = s - (float)(KK - c);
                float bic = ds * ds * invC + EPSV * __logf(sg) - lc[c];
                rowacc += sg * sinv[c];
#pragma unroll
                for (int r = 0; r < 5; r++) y[r] += bic * w2[r * 65536 + i * 16 + c];
            }
            float last = (1.0f - rowacc) * MUV;
            last = fminf(fmaxf(last, SMALLV), 1.0f - SMALLV);
            float b15 = s * s * invC + EPSV * __logf(last);
#pragma unroll
            for (int r = 0; r < 5; r++) y[r] += b15 * w2[r * 65536 + i * 16 + 15];
        }
#pragma unroll
        for (int r = 0; r < 5; r++) y[r] = warp_sum(y[r]);
        if (!lane) {
#pragma unroll
            for (int r = 0; r < 5; r++) sy[wid][r] = y[r];
        }
        __syncthreads();
        if (tid < 5) {
            float a = 0.0f;
            for (int w = 0; w < 16; w++) a += sy[w][tid];
            yf[tid] = a;
        }
        __syncthreads();
        if (tid < KK) {
            float g = 0.0f;
#pragma unroll
            for (int r = 0; r < 5; r++) g += yf[r] * w1[(NN + tid) * 5 + r];
            gg[tid] = g;
        }
        __syncthreads();
        if (tid < 16) {
            int m = tid;
            float w = (m == 0) ? 1.0f
                     : __expf(10.0f * gg[KK - m] - g_P.alpha * (float)(m * m));
            g_w[b * 16 + m] = w;
        }
    }
}

// ---------------- fused main: 200-iter Sinkhorn + output + norm ----------------
__global__ __launch_bounds__(256, 1) void kMain(const float* __restrict__ scores,
                                                float* __restrict__ out) {
    int b = blockIdx.x, tid = threadIdx.x, lane = tid & 31, wid = tid >> 5;  // 8 warps
    __shared__ float sS[2][8][16];
    __shared__ float sinv[KK];
    float c2 = g_P.c_exp2;
    const float2* sc2 = reinterpret_cast<const float2*>(scores + b * NN);
    float2* t2out = reinterpret_cast<float2*>(g_t + b * NN);

    // p values as 8 packed pairs; even powers x^2..x^14 are iteration-invariant
    ull X[8];
    ull P[8][7];
#pragma unroll
    for (int p = 0; p < 8; p++) {
        float2 s = sc2[tid + p * 256];
        float xlo = exp2f(c2 * fixs(s.x));
        float xhi = exp2f(c2 * fixs(s.y));
        ull x = pk2(xlo, xhi);
        X[p] = x;
        ull x2 = mul2(x, x);
        P[p][0] = x2;
#pragma unroll
        for (int j = 1; j < 7; j++) P[p][j] = mul2(P[p][j - 1], x2);
    }
    ull W[16];
#pragma unroll
    for (int m = 0; m < 16; m++) { float v = g_w[b * 16 + m]; W[m] = pk2(v, v); }

    for (int it = 0; it < NITER; it++) {
        ull S[16];
#pragma unroll
        for (int m = 0; m < 16; m++) S[m] = 0ull;
#pragma unroll
        for (int p = 0; p < 8; p++) {
            ull x2 = P[p][0];
            // H = A(x^2) + x*B(x^2)
            ull A = W[14], B = W[15];
#pragma unroll
            for (int j = 6; j >= 1; j--) {
                A = fma2(A, x2, W[2 * j]);
                B = fma2(B, x2, W[2 * j + 1]);
            }
            A = fma2(A, x2, W[0]);
            B = fma2(B, x2, W[1]);
            ull H = fma2(X[p], B, A);
            float hlo, hhi; upk2(hlo, hhi, H);
            float tlo = MUV * rcpa(hlo);
            float thi = MUV * rcpa(hhi);
            if (it == NITER - 1) t2out[tid + p * 256] = make_float2(tlo, thi);
            ull t = pk2(tlo, thi);
            ull tx = mul2(t, X[p]);
            S[0] = add2(S[0], t);
            S[1] = add2(S[1], tx);
#pragma unroll
            for (int j = 1; j < 8; j++) {
                S[2 * j]     = fma2(t,  P[p][j - 1], S[2 * j]);
                S[2 * j + 1] = fma2(tx, P[p][j - 1], S[2 * j + 1]);
            }
        }
        // pairwise halves
        float v[16];
#pragma unroll
        for (int m = 0; m < 16; m++) { float lo, hi; upk2(lo, hi, S[m]); v[m] = lo + hi; }
        // index-matched butterfly: value m's bit j follows lane bit j (15 shfl)
        float u8[8];
#pragma unroll
        for (int q = 0; q < 8; q++) {
            bool h = lane & 1;
            float keep = h ? v[2 * q + 1] : v[2 * q];
            float send = h ? v[2 * q] : v[2 * q + 1];
            u8[q] = keep + __shfl_xor_sync(0xffffffffu, send, 1);
        }
        float u4[4];
#pragma unroll
        for (int q = 0; q < 4; q++) {
            bool h = lane & 2;
            float keep = h ? u8[2 * q + 1] : u8[2 * q];
            float send = h ? u8[2 * q] : u8[2 * q + 1];
            u4[q] = keep + __shfl_xor_sync(0xffffffffu, send, 2);
        }
        float u2[2];
#pragma unroll
        for (int q = 0; q < 2; q++) {
            bool h = lane & 4;
            float keep = h ? u2[0] : u2[0]; // placeholder; real below
            (void)keep;
            float k2 = (lane & 4) ? u4[2 * q + 1] : u4[2 * q];
            float s2 = (lane & 4) ? u4[2 * q] : u4[2 * q + 1];
            u2[q] = k2 + __shfl_xor_sync(0xffffffffu, s2, 4);
        }
        float k1 = (lane & 8) ? u2[1] : u2[0];
        float s1 = (lane & 8) ? u2[0] : u2[1];
        float u1 = k1 + __shfl_xor_sync(0xffffffffu, s1, 8);
        float tot = u1 + __shfl_xor_sync(0xffffffffu, u1, 16);
        // tot = warp total for index m = lane & 15
        int par = it & 1;
        if (lane < 16) sS[par][wid][lane] = tot;
        __syncthreads();
        int m = lane & 15;
        float a = 0.0f;
#pragma unroll
        for (int q = 0; q < 8; q++) a += sS[par][q][m];
        float nu = (m == 0) ? NU0 : MUV;
        float wv = nu * rcpa(a);
#pragma unroll
        for (int m2 = 0; m2 < 16; m2++) {
            float x = __shfl_sync(0xffffffffu, wv, m2);
            W[m2] = pk2(x, x);
        }
    }

    // ---- epilogue: Gamma, output A, norm ----
    if (tid < KK) sinv[tid] = 1.0f / g_colsum[b * KK + tid];
    __syncthreads();
    float nacc = 0.0f;
#pragma unroll
    for (int p = 0; p < 8; p++) {
        float2 tv = t2out[tid + p * 256];
        ull t = pk2(tv.x, tv.y);
        ull tx = mul2(t, X[p]);
        ull gp[16];
        gp[0] = mul2(t, W[0]);
        gp[1] = mul2(tx, W[1]);
#pragma unroll
        for (int j = 1; j < 8; j++) {
            gp[2 * j]     = mul2(mul2(t,  P[p][j - 1]), W[2 * j]);
            gp[2 * j + 1] = mul2(mul2(tx, P[p][j - 1]), W[2 * j + 1]);
        }
        float glo[16], ghi[16];
#pragma unroll
        for (int m = 0; m < 16; m++) upk2(glo[m], ghi[m], gp[m]);
        int e0 = 2 * (tid + p * 256);
        float* Ao0 = out + ((size_t)(b * NN + e0)) * 15;
        float* Ao1 = Ao0 + 15;
#pragma unroll
        for (int c = 0; c < KK; c++) {
            Ao0[c] = 4096.0f * glo[15 - c];
            Ao1[c] = 4096.0f * ghi[15 - c];
        }
        float racc0 = 0.0f, racc1 = 0.0f;
#pragma unroll
        for (int c = 0; c < KK; c++) {
            const float2 sg2 = *reinterpret_cast<const float2*>(
                &g_sig[(b * KK + c) * NN + e0]);
            float sn0 = sg2.x * sinv[c];
            float sn1 = sg2.y * sinv[c];
            racc0 += sn0; racc1 += sn1;
            float d0 = glo[15 - c] - sn0 * MUV;
            float d1 = ghi[15 - c] - sn1 * MUV;
            nacc += d0 * d0 + d1 * d1;
        }
        float l0 = fminf(fmaxf((1.0f - racc0) * MUV, SMALLV), 1.0f - SMALLV);
        float l1 = fminf(fmaxf((1.0f - racc1) * MUV, SMALLV), 1.0f - SMALLV);
        float d0 = glo[0] - l0, d1 = ghi[0] - l1;
        nacc += d0 * d0 + d1 * d1;
    }
    nacc = warp_sum(nacc);
    __shared__ float snrm[8];
    if (!lane) snrm[wid] = nacc;
    __syncthreads();
    if (tid == 0) {
        float a = 0.0f;
        for (int q = 0; q < 8; q++) a += snrm[q];
        atomicAdd(&g_norm, (double)a);
    }
}

__global__ void kFin(float* __restrict__ out, int out_size) {
    if (threadIdx.x == 0) out[out_size - 1] = sqrtf((float)g_norm);
}

extern "C" void kernel_launch(void* const* d_in, const int* in_sizes, int n_in,
                              void* d_out, int out_size) {
    const float* scores = (const float*)d_in[0];
    const float* tau    = (const float*)d_in[1];
    const float* w1     = (const float*)d_in[2];
    const float* w2     = (const float*)d_in[3];
    float* out = (float*)d_out;
    kA1<<<256, 256>>>(scores);
    kA2<<<1, 256>>>(tau);
    kPre<<<NB, 512>>>(scores, w1, w2);
    kMain<<<NB, 256>>>(scores, out);
    kFin<<<1, 1>>>(out, out_size);
}

// round 5
// speedup vs baseline: 1.5153x; 1.1068x over previous
#include <cuda_runtime.h>
#include <math.h>

#define NB 128
#define NN 4096
#define KK 15
#define EPSV 0.1f
#define SMALLV 1e-20f
#define MUV 2.44140625e-4f   /* 1/4096 */
#define NU0 (4081.0f/4096.0f)
#define NITER 200

typedef unsigned long long ull;

// ---------------- device scratch (static, no allocation) ----------------
__device__ float g_sig[NB * KK * NN];   // sigmoid+SMALL, layout [b][j][i]
__device__ float g_colsum[NB * KK];     // per-(b,j) column sums of sig
__device__ float g_w[NB * 16];          // initial Sinkhorn state w_m
__device__ float g_t[NB * NN];          // t_i from final iteration
__device__ float g_mx[256], g_mn[256];
__device__ int   g_fl[256];
__device__ double g_norm;

struct Par { float filled, invCmax, alpha, inv_tau, c_exp2; };
__device__ Par g_P;

// ---------------- helpers ----------------
__device__ __forceinline__ float warp_sum(float v) {
#pragma unroll
    for (int o = 16; o > 0; o >>= 1) v += __shfl_xor_sync(0xffffffffu, v, o);
    return v;
}
__device__ __forceinline__ float warp_max(float v) {
#pragma unroll
    for (int o = 16; o > 0; o >>= 1) v = fmaxf(v, __shfl_xor_sync(0xffffffffu, v, o));
    return v;
}
__device__ __forceinline__ float warp_min(float v) {
#pragma unroll
    for (int o = 16; o > 0; o >>= 1) v = fminf(v, __shfl_xor_sync(0xffffffffu, v, o));
    return v;
}
__device__ __forceinline__ int warp_or(int v) {
#pragma unroll
    for (int o = 16; o > 0; o >>= 1) v |= __shfl_xor_sync(0xffffffffu, v, o);
    return v;
}
__device__ __forceinline__ float rcpa(float x) {
    float y; asm("rcp.approx.f32 %0, %1;" : "=f"(y) : "f"(x)); return y;
}
__device__ __forceinline__ float fixs(float s) {
    return (isinf(s) && s < 0.0f) ? g_P.filled : s;
}

// ---------------- packed f32x2 (sm_103a) ----------------
__device__ __forceinline__ ull pk2(float lo, float hi) {
    ull r; asm("mov.b64 %0, {%1,%2};" : "=l"(r) : "f"(lo), "f"(hi)); return r;
}
__device__ __forceinline__ void upk2(float& lo, float& hi, ull v) {
    asm("mov.b64 {%0,%1}, %2;" : "=f"(lo), "=f"(hi) : "l"(v));
}
__device__ __forceinline__ ull fma2(ull a, ull b, ull c) {
    ull d; asm("fma.rn.f32x2 %0, %1, %2, %3;" : "=l"(d) : "l"(a), "l"(b), "l"(c)); return d;
}
__device__ __forceinline__ ull mul2(ull a, ull b) {
    ull d; asm("mul.rn.f32x2 %0, %1, %2;" : "=l"(d) : "l"(a), "l"(b)); return d;
}
__device__ __forceinline__ ull add2(ull a, ull b) {
    ull d; asm("add.rn.f32x2 %0, %1, %2;" : "=l"(d) : "l"(a), "l"(b)); return d;
}

// ---------------- A1: global min/max partials ----------------
__global__ void kA1(const float* __restrict__ scores) {
    int tid = threadIdx.x;
    int base = blockIdx.x * 2048 + tid * 8;
    const float4* p4 = reinterpret_cast<const float4*>(scores + base);
    float4 a = p4[0], b = p4[1];
    float vs[8] = {a.x, a.y, a.z, a.w, b.x, b.y, b.z, b.w};
    float mx = -3.4e38f, mn = 3.4e38f; int fl = 0;
#pragma unroll
    for (int t = 0; t < 8; t++) {
        float x = vs[t];
        if (isinf(x) && x < 0.0f) fl = 1;
        else mn = fminf(mn, x);
        mx = fmaxf(mx, x);
    }
    mx = warp_max(mx); mn = warp_min(mn); fl = warp_or(fl);
    __shared__ float smx[8], smn[8]; __shared__ int sfl[8];
    int lane = tid & 31, wid = tid >> 5;
    if (!lane) { smx[wid] = mx; smn[wid] = mn; sfl[wid] = fl; }
    __syncthreads();
    if (tid == 0) {
        for (int w = 1; w < 8; w++) { mx = fmaxf(mx, smx[w]); mn = fminf(mn, smn[w]); fl |= sfl[w]; }
        g_mx[blockIdx.x] = mx; g_mn[blockIdx.x] = mn; g_fl[blockIdx.x] = fl;
    }
}

// ---------------- A2: finalize scalar params ----------------
__global__ void kA2(const float* __restrict__ tau) {
    int tid = threadIdx.x, lane = tid & 31, wid = tid >> 5;
    float mx = g_mx[tid], mn = g_mn[tid]; int fl = g_fl[tid];
    mx = warp_max(mx); mn = warp_min(mn); fl = warp_or(fl);
    __shared__ float smx[8], smn[8]; __shared__ int sfl[8];
    if (!lane) { smx[wid] = mx; smn[wid] = mn; sfl[wid] = fl; }
    __syncthreads();
    if (tid == 0) {
        for (int w = 1; w < 8; w++) { mx = fmaxf(mx, smx[w]); mn = fminf(mn, smn[w]); fl |= sfl[w]; }
        float filled = mn - (mx - mn);
        float lo = fl ? filled : mn;
        float d1 = lo - 15.0f, d2 = mx - 15.0f;
        float Cmax = fmaxf(fmaxf(lo * lo, d1 * d1), fmaxf(mx * mx, d2 * d2));
        float invC = 1.0f / Cmax;
        Par P;
        P.filled = filled; P.invCmax = invC; P.alpha = 10.0f * invC;
        P.inv_tau = 1.0f / tau[0];
        P.c_exp2 = 2.0f * (10.0f * invC) * 1.4426950408889634f;
        g_P = P;
        g_norm = 0.0;
    }
}

// ---------------- fused prepass: top-15, sigmoids+colsums, rank-5 warm start ----------------
__global__ __launch_bounds__(512) void kPre(const float* __restrict__ scores,
                                            const float* __restrict__ w1,
                                            const float* __restrict__ w2) {
    int b = blockIdx.x, tid = threadIdx.x, lane = tid & 31, wid = tid >> 5;
    __shared__ float stv[KK];
    __shared__ float swm[16];
    __shared__ float sbc;
    __shared__ int claim;
    __shared__ float scs[16][KK];
    __shared__ float sinv[KK], lc[KK];
    __shared__ float sy[16][5];
    __shared__ float yf[5];
    __shared__ float gg[KK];

    // ---- phase A: top-15 via 15 masked argmax rounds ----
    {
        const float4* p4 = reinterpret_cast<const float4*>(scores + b * NN) + tid * 2;
        float4 a = p4[0], c4 = p4[1];
        float v[8] = {a.x, a.y, a.z, a.w, c4.x, c4.y, c4.z, c4.w};
#pragma unroll
        for (int e = 0; e < 8; e++) v[e] = fixs(v[e]);
        for (int r = 0; r < KK; r++) {
            float lm = v[0];
#pragma unroll
            for (int e = 1; e < 8; e++) lm = fmaxf(lm, v[e]);
            lm = warp_max(lm);
            if (!lane) swm[wid] = lm;
            __syncthreads();
            if (tid == 0) {
                float m = swm[0];
                for (int w = 1; w < 16; w++) m = fmaxf(m, swm[w]);
                sbc = m; claim = 0;
                stv[r] = m;
            }
            __syncthreads();
            float m = sbc;
            int idx = -1;
#pragma unroll
            for (int e = 0; e < 8; e++) if (idx < 0 && v[e] == m) idx = e;
            if (idx >= 0) {
                int old = atomicAdd(&claim, 1);
                if (old == 0) v[idx] = -3.4e38f;
            }
        }
    }
    __syncthreads();

    // ---- phase B: sigmoids + column sums ----
    {
        float itau = g_P.inv_tau;
        float cs[KK];
#pragma unroll
        for (int j = 0; j < KK; j++) cs[j] = 0.0f;
        for (int e = 0; e < 8; e++) {
            int i = tid + e * 512;
            float s = fixs(scores[b * NN + i]);
#pragma unroll
            for (int j = 0; j < KK; j++) {
                float d = fabsf(stv[j] - s) * itau;
                float ex = __expf(d);
                float sg = rcpa(1.0f + ex) + SMALLV;
                g_sig[(b * KK + j) * NN + i] = sg;
                cs[j] += sg;
            }
        }
#pragma unroll
        for (int j = 0; j < KK; j++) cs[j] = warp_sum(cs[j]);
        if (!lane) {
#pragma unroll
            for (int j = 0; j < KK; j++) scs[wid][j] = cs[j];
        }
        __syncthreads();
        if (tid < KK) {
            float a = 0.0f;
            for (int w = 0; w < 16; w++) a += scs[w][tid];
            g_colsum[b * KK + tid] = a;
            sinv[tid] = 1.0f / a;
            lc[tid] = EPSV * __logf(4096.0f * a);
        }
    }
    __syncthreads();

    // ---- phase C: rank-5 projection -> initial w (float4 loads of w2) ----
    {
        float invC = g_P.invCmax;
        float y[5] = {0, 0, 0, 0, 0};
        for (int e = 0; e < 8; e++) {
            int i = tid + e * 512;
            float s = fixs(scores[b * NN + i]);
            float bb[16];
            float rowacc = 0.0f;
#pragma unroll
            for (int c = 0; c < KK; c++) {
                float sg = g_sig[(b * KK + c) * NN + i];
                float ds = s - (float)(KK - c);
                bb[c] = ds * ds * invC + EPSV * __logf(sg) - lc[c];
                rowacc += sg * sinv[c];
            }
            float last = (1.0f - rowacc) * MUV;
            last = fminf(fmaxf(last, SMALLV), 1.0f - SMALLV);
            bb[15] = s * s * invC + EPSV * __logf(last);
#pragma unroll
            for (int r = 0; r < 5; r++) {
                const float4* wv = reinterpret_cast<const float4*>(w2 + r * 65536 + i * 16);
                float4 a0 = wv[0], a1 = wv[1], a2 = wv[2], a3 = wv[3];
                float acc = bb[0] * a0.x + bb[1] * a0.y + bb[2] * a0.z + bb[3] * a0.w;
                acc += bb[4] * a1.x + bb[5] * a1.y + bb[6] * a1.z + bb[7] * a1.w;
                acc += bb[8] * a2.x + bb[9] * a2.y + bb[10] * a2.z + bb[11] * a2.w;
                acc += bb[12] * a3.x + bb[13] * a3.y + bb[14] * a3.z + bb[15] * a3.w;
                y[r] += acc;
            }
        }
#pragma unroll
        for (int r = 0; r < 5; r++) y[r] = warp_sum(y[r]);
        if (!lane) {
#pragma unroll
            for (int r = 0; r < 5; r++) sy[wid][r] = y[r];
        }
        __syncthreads();
        if (tid < 5) {
            float a = 0.0f;
            for (int w = 0; w < 16; w++) a += sy[w][tid];
            yf[tid] = a;
        }
        __syncthreads();
        if (tid < KK) {
            float g = 0.0f;
#pragma unroll
            for (int r = 0; r < 5; r++) g += yf[r] * w1[(NN + tid) * 5 + r];
            gg[tid] = g;
        }
        __syncthreads();
        if (tid < 16) {
            int m = tid;
            float w = (m == 0) ? 1.0f
                     : __expf(10.0f * gg[KK - m] - g_P.alpha * (float)(m * m));
            g_w[b * 16 + m] = w;
        }
    }
}

// ---------------- fused main: 200-iter Sinkhorn + output + norm ----------------
__global__ __launch_bounds__(256, 1) void kMain(const float* __restrict__ scores,
                                                float* __restrict__ out) {
    int b = blockIdx.x, tid = threadIdx.x, lane = tid & 31, wid = tid >> 5;  // 8 warps
    __shared__ float sS[2][8][16];
    __shared__ float sinv[KK];
    float c2 = g_P.c_exp2;
    const float2* sc2 = reinterpret_cast<const float2*>(scores + b * NN);
    float2* t2out = reinterpret_cast<float2*>(g_t + b * NN);

    // per pair: x, x^2, x^4, x^8, x^12 (10 regs/pair) — iteration-invariant
    ull X[8], X2[8], X4[8], X8[8], X12[8];
#pragma unroll
    for (int p = 0; p < 8; p++) {
        float2 s = sc2[tid + p * 256];
        float xlo = exp2f(c2 * fixs(s.x));
        float xhi = exp2f(c2 * fixs(s.y));
        ull x = pk2(xlo, xhi);
        X[p] = x;
        X2[p] = mul2(x, x);
        X4[p] = mul2(X2[p], X2[p]);
        X8[p] = mul2(X4[p], X4[p]);
        X12[p] = mul2(X8[p], X4[p]);
    }
    ull W[16];
#pragma unroll
    for (int m = 0; m < 16; m++) { float v = g_w[b * 16 + m]; W[m] = pk2(v, v); }

    for (int it = 0; it < NITER; it++) {
        ull S[16];
#pragma unroll
        for (int m = 0; m < 16; m++) S[m] = 0ull;
#pragma unroll
        for (int p = 0; p < 8; p++) {
            ull x2 = X2[p];
            // H = A(x^2) + x*B(x^2)
            ull A = W[14], B = W[15];
#pragma unroll
            for (int j = 6; j >= 1; j--) {
                A = fma2(A, x2, W[2 * j]);
                B = fma2(B, x2, W[2 * j + 1]);
            }
            A = fma2(A, x2, W[0]);
            B = fma2(B, x2, W[1]);
            ull H = fma2(X[p], B, A);
            float hlo, hhi; upk2(hlo, hhi, H);
            float tlo = MUV * rcpa(hlo);
            float thi = MUV * rcpa(hhi);
            if (it == NITER - 1) t2out[tid + p * 256] = make_float2(tlo, thi);
            ull t = pk2(tlo, thi);
            ull tx = mul2(t, X[p]);
            ull t2 = mul2(t, x2);
            ull t3 = mul2(tx, x2);
            S[0] = add2(S[0], t);
            S[1] = add2(S[1], tx);
            S[2] = add2(S[2], t2);
            S[3] = add2(S[3], t3);
            S[4] = fma2(t, X4[p], S[4]);
            S[5] = fma2(tx, X4[p], S[5]);
            S[6] = fma2(t2, X4[p], S[6]);
            S[7] = fma2(t3, X4[p], S[7]);
            S[8] = fma2(t, X8[p], S[8]);
            S[9] = fma2(tx, X8[p], S[9]);
            S[10] = fma2(t2, X8[p], S[10]);
            S[11] = fma2(t3, X8[p], S[11]);
            S[12] = fma2(t, X12[p], S[12]);
            S[13] = fma2(tx, X12[p], S[13]);
            S[14] = fma2(t2, X12[p], S[14]);
            S[15] = fma2(t3, X12[p], S[15]);
        }
        // pairwise halves
        float v[16];
#pragma unroll
        for (int m = 0; m < 16; m++) { float lo, hi; upk2(lo, hi, S[m]); v[m] = lo + hi; }
        // index-matched butterfly: value m's bit j follows lane bit j (16 shfl total)
        float u8[8];
#pragma unroll
        for (int q = 0; q < 8; q++) {
            float keep = (lane & 1) ? v[2 * q + 1] : v[2 * q];
            float send = (lane & 1) ? v[2 * q] : v[2 * q + 1];
            u8[q] = keep + __shfl_xor_sync(0xffffffffu, send, 1);
        }
        float u4[4];
#pragma unroll
        for (int q = 0; q < 4; q++) {
            float keep = (lane & 2) ? u8[2 * q + 1] : u8[2 * q];
            float send = (lane & 2) ? u8[2 * q] : u8[2 * q + 1];
            u4[q] = keep + __shfl_xor_sync(0xffffffffu, send, 2);
        }
        float u2[2];
#pragma unroll
        for (int q = 0; q < 2; q++) {
            float keep = (lane & 4) ? u4[2 * q + 1] : u4[2 * q];
            float send = (lane & 4) ? u4[2 * q] : u4[2 * q + 1];
            u2[q] = keep + __shfl_xor_sync(0xffffffffu, send, 4);
        }
        float k1 = (lane & 8) ? u2[1] : u2[0];
        float s1 = (lane & 8) ? u2[0] : u2[1];
        float u1 = k1 + __shfl_xor_sync(0xffffffffu, s1, 8);
        float tot = u1 + __shfl_xor_sync(0xffffffffu, u1, 16);
        // tot = warp total for index m = lane & 15
        int par = it & 1;
        if (lane < 16) sS[par][wid][lane] = tot;
        __syncthreads();
        int m = lane & 15;
        float a = 0.0f;
#pragma unroll
        for (int q = 0; q < 8; q++) a += sS[par][q][m];
        float nu = (m == 0) ? NU0 : MUV;
        float wv = nu * rcpa(a);
#pragma unroll
        for (int m2 = 0; m2 < 16; m2++) {
            float x = __shfl_sync(0xffffffffu, wv, m2);
            W[m2] = pk2(x, x);
        }
    }

    // ---- epilogue: Gamma, output A, norm ----
    if (tid < KK) sinv[tid] = 1.0f / g_colsum[b * KK + tid];
    __syncthreads();
    float nacc = 0.0f;
#pragma unroll
    for (int p = 0; p < 8; p++) {
        float2 tv = t2out[tid + p * 256];
        ull t = pk2(tv.x, tv.y);
        ull tx = mul2(t, X[p]);
        ull t2 = mul2(t, X2[p]);
        ull t3 = mul2(tx, X2[p]);
        ull gp[16];
        gp[0] = mul2(t, W[0]);
        gp[1] = mul2(tx, W[1]);
        gp[2] = mul2(t2, W[2]);
        gp[3] = mul2(t3, W[3]);
        gp[4] = mul2(mul2(t, X4[p]), W[4]);
        gp[5] = mul2(mul2(tx, X4[p]), W[5]);
        gp[6] = mul2(mul2(t2, X4[p]), W[6]);
        gp[7] = mul2(mul2(t3, X4[p]), W[7]);
        gp[8] = mul2(mul2(t, X8[p]), W[8]);
        gp[9] = mul2(mul2(tx, X8[p]), W[9]);
        gp[10] = mul2(mul2(t2, X8[p]), W[10]);
        gp[11] = mul2(mul2(t3, X8[p]), W[11]);
        gp[12] = mul2(mul2(t, X12[p]), W[12]);
        gp[13] = mul2(mul2(tx, X12[p]), W[13]);
        gp[14] = mul2(mul2(t2, X12[p]), W[14]);
        gp[15] = mul2(mul2(t3, X12[p]), W[15]);
        float glo[16], ghi[16];
#pragma unroll
        for (int m = 0; m < 16; m++) upk2(glo[m], ghi[m], gp[m]);
        int e0 = 2 * (tid + p * 256);
        float* Ao0 = out + ((size_t)(b * NN + e0)) * 15;
        float* Ao1 = Ao0 + 15;
#pragma unroll
        for (int c = 0; c < KK; c++) {
            Ao0[c] = 4096.0f * glo[15 - c];
            Ao1[c] = 4096.0f * ghi[15 - c];
        }
        float racc0 = 0.0f, racc1 = 0.0f;
#pragma unroll
        for (int c = 0; c < KK; c++) {
            const float2 sg2 = *reinterpret_cast<const float2*>(
                &g_sig[(b * KK + c) * NN + e0]);
            float sn0 = sg2.x * sinv[c];
            float sn1 = sg2.y * sinv[c];
            racc0 += sn0; racc1 += sn1;
            float d0 = glo[15 - c] - sn0 * MUV;
            float d1 = ghi[15 - c] - sn1 * MUV;
            nacc += d0 * d0 + d1 * d1;
        }
        float l0 = fminf(fmaxf((1.0f - racc0) * MUV, SMALLV), 1.0f - SMALLV);
        float l1 = fminf(fmaxf((1.0f - racc1) * MUV, SMALLV), 1.0f - SMALLV);
        float d0 = glo[0] - l0, d1 = ghi[0] - l1;
        nacc += d0 * d0 + d1 * d1;
    }
    nacc = warp_sum(nacc);
    __shared__ float snrm[8];
    if (!lane) snrm[wid] = nacc;
    __syncthreads();
    if (tid == 0) {
        float a = 0.0f;
        for (int q = 0; q < 8; q++) a += snrm[q];
        atomicAdd(&g_norm, (double)a);
    }
}

__global__ void kFin(float* __restrict__ out, int out_size) {
    if (threadIdx.x == 0) out[out_size - 1] = sqrtf((float)g_norm);
}

extern "C" void kernel_launch(void* const* d_in, const int* in_sizes, int n_in,
                              void* d_out, int out_size) {
    const float* scores = (const float*)d_in[0];
    const float* tau    = (const float*)d_in[1];
    const float* w1     = (const float*)d_in[2];
    const float* w2     = (const float*)d_in[3];
    float* out = (float*)d_out;
    kA1<<<256, 256>>>(scores);
    kA2<<<1, 256>>>(tau);
    kPre<<<NB, 512>>>(scores, w1, w2);
    kMain<<<NB, 256>>>(scores, out);
    kFin<<<1, 1>>>(out, out_size);
}